// round 16
// baseline (speedup 1.0000x reference)
#include <cuda_runtime.h>
#include <cuda_bf16.h>

#define RX   128
#define DD   64
#define NBU  32
#define NTILE (NBU*RX)   // 4096

// Scratch
__device__ float g_P[NBU*RX*DD];
__device__ float g_B[NBU*RX*DD];
__device__ float g_G[NBU*RX*DD];
__device__ float g_S[NBU*RX*RX];       // <P_i,B_j>
__device__ float g_stats[NBU*RX*8];    // sumP,sumP2,sumB,sumB2,sumG,sumG2,sPG,sBG

typedef unsigned int u32;

__device__ __forceinline__ u32 smem_u32(const void* p) {
    u32 a;
    asm("{ .reg .u64 t; cvta.to.shared.u64 t, %1; cvt.u32.u64 %0, t; }" : "=r"(a) : "l"(p));
    return a;
}

// -------------------------------------------------------------------------
// Kernel 1: P,B,G rows + per-row stats, with the per-bu mean and
// pm/gm (W1 blocks d,e) folded in. grid = (NBU, 8), 512 thr.
// -------------------------------------------------------------------------
#define PREP_SMEM_FLOATS (3*4096 + 16*68 + 3*16*65 + 8*64 + 3*64)
#define PREP_SMEM_BYTES  (PREP_SMEM_FLOATS*4)

__global__ void __launch_bounds__(512) prep_kernel(
    const float* __restrict__ x, const float* __restrict__ W1,
    const float* __restrict__ b1)
{
    extern __shared__ float sm[];
    float* ws  = sm;                    // [3][64][64]
    float* xs  = ws + 3*4096;           // [16][68]
    float* sP  = xs + 16*68;            // [16][65]
    float* sB  = sP + 16*65;
    float* sG  = sB + 16*65;
    float* msp = sG + 16*65;            // [8][64]
    float* mm  = msp + 8*64;            // [64]
    float* pms = mm + 64;               // [64]
    float* gms = pms + 64;              // [64]

    const int bu  = blockIdx.x;
    const int ic0 = blockIdx.y * 16;
    const int t   = threadIdx.x;
    const int wid = t >> 5, lane = t & 31;

    const float* xp = x + (size_t)bu * RX * DD;

    // W1 blocks a,b,c -> smem (float4)
    for (int i4 = t; i4 < 3*1024; i4 += 512) {
        const int blk = i4 >> 10;
        const int rem = i4 & 1023;
        const int o = rem >> 4, k4 = rem & 15;
        const float4 v = *(const float4*)(W1 + (size_t)o*320 + blk*64 + k4*4);
        *(float4*)(ws + blk*4096 + o*64 + k4*4) = v;
    }
    // own 16 x-rows (float4, pitch 68)
    if (t < 256) {
        const int r = t >> 4, c4 = t & 15;
        const float4 v = *(const float4*)(xp + (size_t)(ic0 + r)*DD + c4*4);
        *(float4*)(xs + r*68 + c4*4) = v;
    }
    // mean partials over all 128 rows (coalesced from global)
    {
        const int col = t & 63;
        const int q   = t >> 6;
        float s = 0.f;
        #pragma unroll 4
        for (int r = q*16; r < q*16 + 16; r++) s += xp[(size_t)r*DD + col];
        msp[q*64 + col] = s;
    }
    __syncthreads();
    if (t < DD) {
        float s = 0.f;
        #pragma unroll
        for (int q = 0; q < 8; q++) s += msp[q*64 + t];
        mm[t] = s * (1.f / RX);
    }
    __syncthreads();

    // pm = b1 + W1e@m, gm = W1d@m  (W1 d,e blocks straight from global)
    if (t < 256) {
        const int o  = t >> 2;
        const int kq = t & 3;
        float pv = 0.f, gv = 0.f;
        #pragma unroll
        for (int s = 0; s < 16; s++) {
            const int k = kq*16 + s;
            const float mv = mm[k];
            gv += W1[(size_t)o*320 + 192 + k] * mv;
            pv += W1[(size_t)o*320 + 256 + k] * mv;
        }
        pv += __shfl_xor_sync(0xffffffffu, pv, 1);
        gv += __shfl_xor_sync(0xffffffffu, gv, 1);
        pv += __shfl_xor_sync(0xffffffffu, pv, 2);
        gv += __shfl_xor_sync(0xffffffffu, gv, 2);
        if (kq == 0) { pms[o] = b1[o] + pv; gms[o] = gv; }
    }
    __syncthreads();

    // Phase B: 16 il x 64 o = 1024 tasks, 2/thread; o uniform-ish per warp
    #pragma unroll
    for (int s = 0; s < 2; s++) {
        const int il = lane & 15;
        const int o  = wid*4 + (lane >> 4)*2 + s;
        const float4* xi = (const float4*)(xs + il*68);
        const float4* wa = (const float4*)(ws + 0*4096 + o*64);
        const float4* wb = (const float4*)(ws + 1*4096 + o*64);
        const float4* wc = (const float4*)(ws + 2*4096 + o*64);
        float accP = pms[o], accB = 0.f, accG = gms[o];
        #pragma unroll
        for (int k4 = 0; k4 < 16; k4++) {
            const float4 xv = xi[k4];
            const float4 a = wa[k4];
            const float4 b = wb[k4];
            const float4 c = wc[k4];
            accG += xv.x*a.x + xv.y*a.y + xv.z*a.z + xv.w*a.w;
            accP += xv.x*b.x + xv.y*b.y + xv.z*b.z + xv.w*b.w;
            accB += xv.x*c.x + xv.y*c.y + xv.z*c.z + xv.w*c.w;
        }
        const int off = (bu*RX + ic0 + il)*DD + o;
        g_P[off] = accP;
        g_B[off] = accB;
        g_G[off] = accG;
        sP[il*65 + o] = accP;
        sB[il*65 + o] = accB;
        sG[il*65 + o] = accG;
    }
    __syncthreads();

    // stats: 16 warps x 1 row
    {
        const int row = wid;
        const float p0 = sP[row*65 + lane], p1 = sP[row*65 + lane+32];
        const float b0 = sB[row*65 + lane], b1v = sB[row*65 + lane+32];
        const float q0 = sG[row*65 + lane], q1 = sG[row*65 + lane+32];
        float v0 = p0 + p1;
        float v1 = p0*p0 + p1*p1;
        float v2 = b0 + b1v;
        float v3 = b0*b0 + b1v*b1v;
        float v4 = q0 + q1;
        float v5 = q0*q0 + q1*q1;
        float v6 = p0*q0 + p1*q1;
        float v7 = b0*q0 + b1v*q1;
        #pragma unroll
        for (int m = 16; m > 0; m >>= 1) {
            v0 += __shfl_xor_sync(0xffffffffu, v0, m);
            v1 += __shfl_xor_sync(0xffffffffu, v1, m);
            v2 += __shfl_xor_sync(0xffffffffu, v2, m);
            v3 += __shfl_xor_sync(0xffffffffu, v3, m);
            v4 += __shfl_xor_sync(0xffffffffu, v4, m);
            v5 += __shfl_xor_sync(0xffffffffu, v5, m);
            v6 += __shfl_xor_sync(0xffffffffu, v6, m);
            v7 += __shfl_xor_sync(0xffffffffu, v7, m);
        }
        if (lane == 0) {
            float* so = g_stats + (size_t)(bu*RX + ic0 + row)*8;
            so[0]=v0; so[1]=v1; so[2]=v2; so[3]=v3; so[4]=v4; so[5]=v5; so[6]=v6; so[7]=v7;
        }
    }
}

// -------------------------------------------------------------------------
// Kernel 2: S[bu][i][j] = <P_i, B_j>. grid = (NBU, 4), 256 threads.
// -------------------------------------------------------------------------
__global__ void __launch_bounds__(256) spb_kernel()
{
    const int bu  = blockIdx.x;
    const int ic0 = blockIdx.y * 32;

    __shared__ float Ps[32*68];
    __shared__ float Bs[RX*68];

    const float* Pb = g_P + (size_t)(bu*RX + ic0)*DD;
    for (int t = threadIdx.x; t < 32*DD; t += 256) {
        int r = t >> 6, c = t & 63;
        Ps[r*68 + c] = Pb[t];
    }
    const float* Bb = g_B + (size_t)bu*RX*DD;
    for (int t = threadIdx.x; t < RX*DD; t += 256) {
        int r = t >> 6, c = t & 63;
        Bs[r*68 + c] = Bb[t];
    }
    __syncthreads();

    const int il = threadIdx.x & 31;
    const int jb = threadIdx.x >> 5;
    const float4* pr = (const float4*)(Ps + il*68);
    float* so = g_S + ((size_t)(bu*RX) + ic0 + il)*RX + jb*16;
    #pragma unroll 1
    for (int jo = 0; jo < 16; jo++) {
        const float4* br = (const float4*)(Bs + (jb*16 + jo)*68);
        float a0 = 0.f, a1 = 0.f, a2 = 0.f, a3 = 0.f;
        #pragma unroll
        for (int k4 = 0; k4 < 16; k4++) {
            const float4 p = pr[k4];
            const float4 b = br[k4];
            a0 += p.x*b.x; a1 += p.y*b.y; a2 += p.z*b.z; a3 += p.w*b.w;
        }
        so[jo] = (a0 + a2) + (a1 + a3);
    }
}

// -------------------------------------------------------------------------
// Kernel 3: HMMA main — EXACT Round-9 structure (proven 72 us):
// Bv[16] hoisted per bu, stats via lane-distribution + shfl broadcast,
// smem A round-trip + ldmatrix, separate uint2 Bhi/Blo.
// -------------------------------------------------------------------------
#define SM_B2   0
#define SM_BHI  256
#define SM_BLO  (256 + 8192)
#define SM_AHI  (256 + 16384)
#define SM_ALO  (256 + 16384 + 18432)
#define SM_TOTAL (256 + 16384 + 36864)  // 53504
#define ASTRIDE 144

__device__ __forceinline__ void mma_bf16(
    float &c0, float &c1, float &c2, float &c3,
    u32 a0, u32 a1, u32 a2, u32 a3, u32 b0, u32 b1)
{
    asm volatile(
        "mma.sync.aligned.m16n8k16.row.col.f32.bf16.bf16.f32 "
        "{%0,%1,%2,%3}, {%4,%5,%6,%7}, {%8,%9}, {%0,%1,%2,%3};"
        : "+f"(c0), "+f"(c1), "+f"(c2), "+f"(c3)
        : "r"(a0), "r"(a1), "r"(a2), "r"(a3), "r"(b0), "r"(b1));
}
__device__ __forceinline__ void ldmat4(u32 r[4], u32 addr) {
    asm volatile("ldmatrix.sync.aligned.m8n8.x4.shared.b16 {%0,%1,%2,%3}, [%4];"
        : "=r"(r[0]), "=r"(r[1]), "=r"(r[2]), "=r"(r[3]) : "r"(addr));
}
__device__ __forceinline__ u32 bf2_u32(float a, float b) {
    __nv_bfloat162 h = __floats2bfloat162_rn(a, b);
    return *(u32*)&h;
}

#define MAIN_PER  14
#define MAIN_GRID ((NTILE + MAIN_PER - 1) / MAIN_PER)   // 293

__global__ void __launch_bounds__(256, 2) main_mma(
    const float* __restrict__ ln_g, const float* __restrict__ ln_b,
    const float* __restrict__ bias, const float* __restrict__ W2,
    const float* __restrict__ b2,   float* __restrict__ out)
{
    extern __shared__ char smem[];
    const u32 sb   = smem_u32(smem);
    const int t    = threadIdx.x;
    const int wid  = t >> 5;
    const int lane = t & 31;

    float* b2s = (float*)(smem + SM_B2);
    uint2* Bhi = (uint2*)(smem + SM_BHI);
    uint2* Blo = (uint2*)(smem + SM_BLO);

    if (t < DD) b2s[t] = b2[t];

    for (int s = t; s < 4*8*32; s += 256) {
        const int ls = s & 31, nt = (s >> 5) & 7, ks = s >> 8;
        const int o  = nt*8 + (ls >> 2);
        const int d  = ks*16 + (ls & 3)*2;
        const float* w = W2 + (size_t)o*DD + d;
        float w0 = w[0], w1 = w[1], w8 = w[8], w9 = w[9];
        __nv_bfloat16 h0 = __float2bfloat16(w0), h1 = __float2bfloat16(w1);
        __nv_bfloat16 h8 = __float2bfloat16(w8), h9 = __float2bfloat16(w9);
        uint2 bh, bl;
        bh.x = ((u32)*(unsigned short*)&h0) | ((u32)*(unsigned short*)&h1 << 16);
        bh.y = ((u32)*(unsigned short*)&h8) | ((u32)*(unsigned short*)&h9 << 16);
        bl.x = bf2_u32(w0 - __bfloat162float(h0), w1 - __bfloat162float(h1));
        bl.y = bf2_u32(w8 - __bfloat162float(h8), w9 - __bfloat162float(h9));
        const int idx = (ks*8 + nt)*32 + ls;
        Bhi[idx] = bh;
        Blo[idx] = bl;
    }
    __syncthreads();

    const int d0 = 2*lane;
    const float lg0 = ln_g[d0], lg1 = ln_g[d0+1];
    const float lbn0 = ln_b[d0], lbn1 = ln_b[d0+1];
    const float bi0 = bias[d0], bi1 = bias[d0+1];

    const int arow = wid*16 + (lane & 15);
    const u32 a_off = (u32)arow*ASTRIDE + (u32)(lane >> 4)*16;
    const u32 ahi_base = sb + SM_AHI + a_off;
    const u32 alo_base = sb + SM_ALO + a_off;

    const int g  = lane >> 2;
    const int t4 = lane & 3;
    const int jl = wid*16 + (lane & 15);    // stats/S distribution row

    const int tile0 = blockIdx.x * MAIN_PER;
    const int tile1 = (tile0 + MAIN_PER < NTILE) ? (tile0 + MAIN_PER) : NTILE;

    int cur_bu = -1;
    float2 Bv[16];
    float  sb_part = 0.f;

    for (int tile = tile0; tile < tile1; tile++) {
        const int bu = tile >> 7;
        const int i  = tile & 127;
        const size_t row = (size_t)bu*RX + i;
        const float* st  = g_stats + (size_t)bu*RX*8;

        if (bu != cur_bu) {
            cur_bu = bu;
            const float* Bb = g_B + (size_t)bu*RX*DD;
            #pragma unroll
            for (int jo = 0; jo < 16; jo++)
                Bv[jo] = *(const float2*)(Bb + (size_t)(wid*16 + jo)*DD + d0);
            sb_part = st[jl*8 + 2 + (lane >> 4)];   // sumB / sumB2
        }

        const float2 P2  = *(const float2*)(g_P + row*DD + d0);
        const float2 G2  = *(const float2*)(g_G + row*DD + d0);
        const float2 spi = *(const float2*)(st + i*8);
        const float4 sdi = *(const float4*)(st + i*8 + 4);
        const float  S_part = g_S[row*RX + jl];

        __syncwarp();
        #pragma unroll
        for (int jo = 0; jo < 16; jo++) {
            const int j = wid*16 + jo;
            const float sumB  = __shfl_sync(0xffffffffu, sb_part, jo);
            const float sumB2 = __shfl_sync(0xffffffffu, sb_part, 16 + jo);
            const float Sij   = __shfl_sync(0xffffffffu, S_part, jo);
            float h0  = P2.x + Bv[jo].x;
            float h1  = P2.y + Bv[jo].y;
            float sum = spi.x + sumB;
            float e2  = spi.y + sumB2 + 2.f*Sij;
            const bool diag = (j == i);
            if (diag) {
                h0 += G2.x; h1 += G2.y;
                sum += sdi.x;
                e2  += sdi.y + 2.f*(sdi.z + sdi.w);
            }
            const float mu  = sum * (1.f/64.f);
            const float var = e2 * (1.f/64.f) - mu*mu;
            const float rs  = rsqrtf(var + 1e-5f);
            float y0 = fmaxf((h0 - mu)*rs*lg0 + lbn0, 0.f);
            float y1 = fmaxf((h1 - mu)*rs*lg1 + lbn1, 0.f);
            if (diag) { y0 += bi0; y1 += bi1; }

            __nv_bfloat16 hh0 = __float2bfloat16(y0);
            __nv_bfloat16 hh1 = __float2bfloat16(y1);
            u32 hiw = ((u32)*(unsigned short*)&hh0) | ((u32)*(unsigned short*)&hh1 << 16);
            u32 low = bf2_u32(y0 - __bfloat162float(hh0), y1 - __bfloat162float(hh1));
            const u32 boff = (u32)j*ASTRIDE + (u32)lane*4;
            *(u32*)(smem + SM_AHI + boff) = hiw;
            *(u32*)(smem + SM_ALO + boff) = low;
        }
        __syncwarp();

        u32 ah[4][4], al[4][4];
        #pragma unroll
        for (int ks = 0; ks < 4; ks++) {
            ldmat4(ah[ks], ahi_base + (u32)ks*32);
            ldmat4(al[ks], alo_base + (u32)ks*32);
        }
        __syncwarp();

        float* obase = out + row*RX*DD;
        #pragma unroll
        for (int nt = 0; nt < 8; nt++) {
            float c0 = 0.f, c1 = 0.f, c2 = 0.f, c3 = 0.f;
            #pragma unroll
            for (int ks = 0; ks < 4; ks++) {
                const int idx = (ks*8 + nt)*32 + lane;
                uint2 bh = Bhi[idx];
                uint2 bl = Blo[idx];
                mma_bf16(c0,c1,c2,c3, ah[ks][0],ah[ks][1],ah[ks][2],ah[ks][3], bh.x, bh.y);
                mma_bf16(c0,c1,c2,c3, ah[ks][0],ah[ks][1],ah[ks][2],ah[ks][3], bl.x, bl.y);
                mma_bf16(c0,c1,c2,c3, al[ks][0],al[ks][1],al[ks][2],al[ks][3], bh.x, bh.y);
            }
            const int o0 = nt*8 + t4*2;
            const float2 bb = *(const float2*)(b2s + o0);
            float2 v0; v0.x = c0 + bb.x; v0.y = c1 + bb.y;
            float2 v1; v1.x = c2 + bb.x; v1.y = c3 + bb.y;
            *(float2*)(obase + (size_t)(wid*16 + g)*DD + o0)     = v0;
            *(float2*)(obase + (size_t)(wid*16 + g + 8)*DD + o0) = v1;
        }
    }
}

// -------------------------------------------------------------------------
// Inputs (metadata order): x, W1, b1, ln_g, ln_b, bias, W2, b2
// -------------------------------------------------------------------------
extern "C" void kernel_launch(void* const* d_in, const int* in_sizes, int n_in,
                              void* d_out, int out_size)
{
    const float* x    = (const float*)d_in[0];
    const float* W1   = (const float*)d_in[1];
    const float* b1   = (const float*)d_in[2];
    const float* ln_g = (const float*)d_in[3];
    const float* ln_b = (const float*)d_in[4];
    const float* bias = (const float*)d_in[5];
    const float* W2   = (const float*)d_in[6];
    const float* b2   = (const float*)d_in[7];
    float* out = (float*)d_out;
    (void)in_sizes; (void)n_in; (void)out_size;

    cudaFuncSetAttribute(prep_kernel, cudaFuncAttributeMaxDynamicSharedMemorySize, PREP_SMEM_BYTES);
    cudaFuncSetAttribute(main_mma, cudaFuncAttributeMaxDynamicSharedMemorySize, SM_TOTAL);

    prep_kernel<<<dim3(NBU, 8), 512, PREP_SMEM_BYTES>>>(x, W1, b1);
    spb_kernel<<<dim3(NBU, 4), 256>>>();
    main_mma<<<MAIN_GRID, 256, SM_TOTAL>>>(ln_g, ln_b, bias, W2, b2, out);
}

// round 17
// speedup vs baseline: 1.3865x; 1.3865x over previous
#include <cuda_runtime.h>
#include <cuda_bf16.h>

#define RX   128
#define DD   64
#define NBU  32
#define NTILE (NBU*RX)   // 4096

// Scratch
__device__ float g_P[NBU*RX*DD];
__device__ float g_B[NBU*RX*DD];
__device__ float g_G[NBU*RX*DD];
__device__ float g_S[NBU*RX*RX];       // <P_i,B_j>
__device__ float g_stats[NBU*RX*8];    // sumP,sumP2,sumB,sumB2,sumG,sumG2,sPG,sBG
__device__ float g_pm[NBU*DD];         // b1 + W1[:,256:320]@m
__device__ float g_gm[NBU*DD];         // W1[:,192:256]@m

typedef unsigned int u32;

__device__ __forceinline__ u32 smem_u32(const void* p) {
    u32 a;
    asm("{ .reg .u64 t; cvta.to.shared.u64 t, %1; cvt.u32.u64 %0, t; }" : "=r"(a) : "l"(p));
    return a;
}

// -------------------------------------------------------------------------
// Kernel 0: per-bu mean + pm/gm. grid = NBU, 256 threads.
// -------------------------------------------------------------------------
__global__ void __launch_bounds__(256) mean_kernel(
    const float* __restrict__ x, const float* __restrict__ W1,
    const float* __restrict__ b1)
{
    __shared__ float msp[4][DD];
    __shared__ float mm[DD];

    const int bu = blockIdx.x;
    const int t  = threadIdx.x;
    const float* xp = x + (size_t)bu * RX * DD;

    {
        const int col = t & 63;
        const int q   = t >> 6;
        float s = 0.f;
        #pragma unroll 8
        for (int r = q*32; r < q*32 + 32; r++) s += xp[(size_t)r*DD + col];
        msp[q][col] = s;
    }
    __syncthreads();
    if (t < DD)
        mm[t] = (msp[0][t] + msp[1][t] + msp[2][t] + msp[3][t]) * (1.f / RX);
    __syncthreads();

    const int o  = t >> 2;
    const int kq = t & 3;
    float pv = 0.f, gv = 0.f;
    #pragma unroll
    for (int s = 0; s < 16; s++) {
        const int k = kq*16 + s;
        const float mv = mm[k];
        gv += W1[(size_t)o*320 + 192 + k] * mv;
        pv += W1[(size_t)o*320 + 256 + k] * mv;
    }
    pv += __shfl_xor_sync(0xffffffffu, pv, 1);
    gv += __shfl_xor_sync(0xffffffffu, gv, 1);
    pv += __shfl_xor_sync(0xffffffffu, pv, 2);
    gv += __shfl_xor_sync(0xffffffffu, gv, 2);
    if (kq == 0) {
        g_pm[bu*DD + o] = b1[o] + pv;
        g_gm[bu*DD + o] = gv;
    }
}

// -------------------------------------------------------------------------
// Kernel 1: P,B,G rows + per-row stats. grid = (NBU, 8), 512 thr.
// -------------------------------------------------------------------------
#define PREP_SMEM_FLOATS (3*4096 + 16*68 + 3*16*65 + 2*64)
#define PREP_SMEM_BYTES  (PREP_SMEM_FLOATS*4)

__global__ void __launch_bounds__(512) prep_kernel(
    const float* __restrict__ x, const float* __restrict__ W1)
{
    extern __shared__ float sm[];
    float* ws  = sm;                    // [3][64][64]
    float* xs  = ws + 3*4096;           // [16][68]
    float* sP  = xs + 16*68;            // [16][65]
    float* sB  = sP + 16*65;
    float* sG  = sB + 16*65;
    float* pms = sG + 16*65;            // [64]
    float* gms = pms + 64;              // [64]

    const int bu  = blockIdx.x;
    const int ic0 = blockIdx.y * 16;
    const int t   = threadIdx.x;
    const int wid = t >> 5, lane = t & 31;

    const float* xp = x + (size_t)bu * RX * DD;

    for (int i4 = t; i4 < 3*1024; i4 += 512) {
        const int blk = i4 >> 10;
        const int rem = i4 & 1023;
        const int o = rem >> 4, k4 = rem & 15;
        const float4 v = *(const float4*)(W1 + (size_t)o*320 + blk*64 + k4*4);
        *(float4*)(ws + blk*4096 + o*64 + k4*4) = v;
    }
    if (t < 256) {
        const int r = t >> 4, c4 = t & 15;
        const float4 v = *(const float4*)(xp + (size_t)(ic0 + r)*DD + c4*4);
        *(float4*)(xs + r*68 + c4*4) = v;
    }
    if (t >= 256 && t < 320) pms[t-256] = g_pm[bu*DD + (t-256)];
    if (t >= 320 && t < 384) gms[t-320] = g_gm[bu*DD + (t-320)];
    __syncthreads();

    #pragma unroll
    for (int s = 0; s < 2; s++) {
        const int il = lane & 15;
        const int o  = wid*4 + (lane >> 4)*2 + s;
        const float4* xi = (const float4*)(xs + il*68);
        const float4* wa = (const float4*)(ws + 0*4096 + o*64);
        const float4* wb = (const float4*)(ws + 1*4096 + o*64);
        const float4* wc = (const float4*)(ws + 2*4096 + o*64);
        float accP = pms[o], accB = 0.f, accG = gms[o];
        #pragma unroll
        for (int k4 = 0; k4 < 16; k4++) {
            const float4 xv = xi[k4];
            const float4 a = wa[k4];
            const float4 b = wb[k4];
            const float4 c = wc[k4];
            accG += xv.x*a.x + xv.y*a.y + xv.z*a.z + xv.w*a.w;
            accP += xv.x*b.x + xv.y*b.y + xv.z*b.z + xv.w*b.w;
            accB += xv.x*c.x + xv.y*c.y + xv.z*c.z + xv.w*c.w;
        }
        const int off = (bu*RX + ic0 + il)*DD + o;
        g_P[off] = accP;
        g_B[off] = accB;
        g_G[off] = accG;
        sP[il*65 + o] = accP;
        sB[il*65 + o] = accB;
        sG[il*65 + o] = accG;
    }
    __syncthreads();

    {
        const int row = wid;
        const float p0 = sP[row*65 + lane], p1 = sP[row*65 + lane+32];
        const float b0 = sB[row*65 + lane], b1v = sB[row*65 + lane+32];
        const float q0 = sG[row*65 + lane], q1 = sG[row*65 + lane+32];
        float v0 = p0 + p1;
        float v1 = p0*p0 + p1*p1;
        float v2 = b0 + b1v;
        float v3 = b0*b0 + b1v*b1v;
        float v4 = q0 + q1;
        float v5 = q0*q0 + q1*q1;
        float v6 = p0*q0 + p1*q1;
        float v7 = b0*q0 + b1v*q1;
        #pragma unroll
        for (int m = 16; m > 0; m >>= 1) {
            v0 += __shfl_xor_sync(0xffffffffu, v0, m);
            v1 += __shfl_xor_sync(0xffffffffu, v1, m);
            v2 += __shfl_xor_sync(0xffffffffu, v2, m);
            v3 += __shfl_xor_sync(0xffffffffu, v3, m);
            v4 += __shfl_xor_sync(0xffffffffu, v4, m);
            v5 += __shfl_xor_sync(0xffffffffu, v5, m);
            v6 += __shfl_xor_sync(0xffffffffu, v6, m);
            v7 += __shfl_xor_sync(0xffffffffu, v7, m);
        }
        if (lane == 0) {
            float* so = g_stats + (size_t)(bu*RX + ic0 + row)*8;
            so[0]=v0; so[1]=v1; so[2]=v2; so[3]=v3; so[4]=v4; so[5]=v5; so[6]=v6; so[7]=v7;
        }
    }
}

// -------------------------------------------------------------------------
// Kernel 2: S[bu][i][j] = <P_i, B_j>. grid = (NBU, 4), 256 threads.
// -------------------------------------------------------------------------
__global__ void __launch_bounds__(256) spb_kernel()
{
    const int bu  = blockIdx.x;
    const int ic0 = blockIdx.y * 32;

    __shared__ float Ps[32*68];
    __shared__ float Bs[RX*68];

    const float* Pb = g_P + (size_t)(bu*RX + ic0)*DD;
    for (int t = threadIdx.x; t < 32*DD; t += 256) {
        int r = t >> 6, c = t & 63;
        Ps[r*68 + c] = Pb[t];
    }
    const float* Bb = g_B + (size_t)bu*RX*DD;
    for (int t = threadIdx.x; t < RX*DD; t += 256) {
        int r = t >> 6, c = t & 63;
        Bs[r*68 + c] = Bb[t];
    }
    __syncthreads();

    const int il = threadIdx.x & 31;
    const int jb = threadIdx.x >> 5;
    const float4* pr = (const float4*)(Ps + il*68);
    float* so = g_S + ((size_t)(bu*RX) + ic0 + il)*RX + jb*16;
    #pragma unroll 1
    for (int jo = 0; jo < 16; jo++) {
        const float4* br = (const float4*)(Bs + (jb*16 + jo)*68);
        float a0 = 0.f, a1 = 0.f, a2 = 0.f, a3 = 0.f;
        #pragma unroll
        for (int k4 = 0; k4 < 16; k4++) {
            const float4 p = pr[k4];
            const float4 b = br[k4];
            a0 += p.x*b.x; a1 += p.y*b.y; a2 += p.z*b.z; a3 += p.w*b.w;
        }
        so[jo] = (a0 + a2) + (a1 + a3);
    }
}

// -------------------------------------------------------------------------
// Kernel 3: HMMA main — Round-9 structure; ONLY change: MAIN_PER 14 -> 16
// (bu-aligned chunks, grid 256, Bv hoist loads exactly once per CTA).
// -------------------------------------------------------------------------
#define SM_B2   0
#define SM_BHI  256
#define SM_BLO  (256 + 8192)
#define SM_AHI  (256 + 16384)
#define SM_ALO  (256 + 16384 + 18432)
#define SM_TOTAL (256 + 16384 + 36864)  // 53504
#define ASTRIDE 144

__device__ __forceinline__ void mma_bf16(
    float &c0, float &c1, float &c2, float &c3,
    u32 a0, u32 a1, u32 a2, u32 a3, u32 b0, u32 b1)
{
    asm volatile(
        "mma.sync.aligned.m16n8k16.row.col.f32.bf16.bf16.f32 "
        "{%0,%1,%2,%3}, {%4,%5,%6,%7}, {%8,%9}, {%0,%1,%2,%3};"
        : "+f"(c0), "+f"(c1), "+f"(c2), "+f"(c3)
        : "r"(a0), "r"(a1), "r"(a2), "r"(a3), "r"(b0), "r"(b1));
}
__device__ __forceinline__ void ldmat4(u32 r[4], u32 addr) {
    asm volatile("ldmatrix.sync.aligned.m8n8.x4.shared.b16 {%0,%1,%2,%3}, [%4];"
        : "=r"(r[0]), "=r"(r[1]), "=r"(r[2]), "=r"(r[3]) : "r"(addr));
}
__device__ __forceinline__ u32 bf2_u32(float a, float b) {
    __nv_bfloat162 h = __floats2bfloat162_rn(a, b);
    return *(u32*)&h;
}

#define MAIN_PER  16
#define MAIN_GRID (NTILE / MAIN_PER)    // 256, bu-aligned

__global__ void __launch_bounds__(256, 2) main_mma(
    const float* __restrict__ ln_g, const float* __restrict__ ln_b,
    const float* __restrict__ bias, const float* __restrict__ W2,
    const float* __restrict__ b2,   float* __restrict__ out)
{
    extern __shared__ char smem[];
    const u32 sb   = smem_u32(smem);
    const int t    = threadIdx.x;
    const int wid  = t >> 5;
    const int lane = t & 31;

    float* b2s = (float*)(smem + SM_B2);
    uint2* Bhi = (uint2*)(smem + SM_BHI);
    uint2* Blo = (uint2*)(smem + SM_BLO);

    if (t < DD) b2s[t] = b2[t];

    for (int s = t; s < 4*8*32; s += 256) {
        const int ls = s & 31, nt = (s >> 5) & 7, ks = s >> 8;
        const int o  = nt*8 + (ls >> 2);
        const int d  = ks*16 + (ls & 3)*2;
        const float* w = W2 + (size_t)o*DD + d;
        float w0 = w[0], w1 = w[1], w8 = w[8], w9 = w[9];
        __nv_bfloat16 h0 = __float2bfloat16(w0), h1 = __float2bfloat16(w1);
        __nv_bfloat16 h8 = __float2bfloat16(w8), h9 = __float2bfloat16(w9);
        uint2 bh, bl;
        bh.x = ((u32)*(unsigned short*)&h0) | ((u32)*(unsigned short*)&h1 << 16);
        bh.y = ((u32)*(unsigned short*)&h8) | ((u32)*(unsigned short*)&h9 << 16);
        bl.x = bf2_u32(w0 - __bfloat162float(h0), w1 - __bfloat162float(h1));
        bl.y = bf2_u32(w8 - __bfloat162float(h8), w9 - __bfloat162float(h9));
        const int idx = (ks*8 + nt)*32 + ls;
        Bhi[idx] = bh;
        Blo[idx] = bl;
    }
    __syncthreads();

    const int d0 = 2*lane;
    const float lg0 = ln_g[d0], lg1 = ln_g[d0+1];
    const float lbn0 = ln_b[d0], lbn1 = ln_b[d0+1];
    const float bi0 = bias[d0], bi1 = bias[d0+1];

    const int arow = wid*16 + (lane & 15);
    const u32 a_off = (u32)arow*ASTRIDE + (u32)(lane >> 4)*16;
    const u32 ahi_base = sb + SM_AHI + a_off;
    const u32 alo_base = sb + SM_ALO + a_off;

    const int g  = lane >> 2;
    const int t4 = lane & 3;
    const int jl = wid*16 + (lane & 15);    // stats/S distribution row

    const int tile0 = blockIdx.x * MAIN_PER;
    const int tile1 = tile0 + MAIN_PER;

    int cur_bu = -1;
    float2 Bv[16];
    float  sb_part = 0.f;

    for (int tile = tile0; tile < tile1; tile++) {
        const int bu = tile >> 7;
        const int i  = tile & 127;
        const size_t row = (size_t)bu*RX + i;
        const float* st  = g_stats + (size_t)bu*RX*8;

        if (bu != cur_bu) {
            cur_bu = bu;
            const float* Bb = g_B + (size_t)bu*RX*DD;
            #pragma unroll
            for (int jo = 0; jo < 16; jo++)
                Bv[jo] = *(const float2*)(Bb + (size_t)(wid*16 + jo)*DD + d0);
            sb_part = st[jl*8 + 2 + (lane >> 4)];   // sumB / sumB2
        }

        const float2 P2  = *(const float2*)(g_P + row*DD + d0);
        const float2 G2  = *(const float2*)(g_G + row*DD + d0);
        const float2 spi = *(const float2*)(st + i*8);
        const float4 sdi = *(const float4*)(st + i*8 + 4);
        const float  S_part = g_S[row*RX + jl];

        __syncwarp();
        #pragma unroll
        for (int jo = 0; jo < 16; jo++) {
            const int j = wid*16 + jo;
            const float sumB  = __shfl_sync(0xffffffffu, sb_part, jo);
            const float sumB2 = __shfl_sync(0xffffffffu, sb_part, 16 + jo);
            const float Sij   = __shfl_sync(0xffffffffu, S_part, jo);
            float h0  = P2.x + Bv[jo].x;
            float h1  = P2.y + Bv[jo].y;
            float sum = spi.x + sumB;
            float e2  = spi.y + sumB2 + 2.f*Sij;
            const bool diag = (j == i);
            if (diag) {
                h0 += G2.x; h1 += G2.y;
                sum += sdi.x;
                e2  += sdi.y + 2.f*(sdi.z + sdi.w);
            }
            const float mu  = sum * (1.f/64.f);
            const float var = e2 * (1.f/64.f) - mu*mu;
            const float rs  = rsqrtf(var + 1e-5f);
            float y0 = fmaxf((h0 - mu)*rs*lg0 + lbn0, 0.f);
            float y1 = fmaxf((h1 - mu)*rs*lg1 + lbn1, 0.f);
            if (diag) { y0 += bi0; y1 += bi1; }

            __nv_bfloat16 hh0 = __float2bfloat16(y0);
            __nv_bfloat16 hh1 = __float2bfloat16(y1);
            u32 hiw = ((u32)*(unsigned short*)&hh0) | ((u32)*(unsigned short*)&hh1 << 16);
            u32 low = bf2_u32(y0 - __bfloat162float(hh0), y1 - __bfloat162float(hh1));
            const u32 boff = (u32)j*ASTRIDE + (u32)lane*4;
            *(u32*)(smem + SM_AHI + boff) = hiw;
            *(u32*)(smem + SM_ALO + boff) = low;
        }
        __syncwarp();

        u32 ah[4][4], al[4][4];
        #pragma unroll
        for (int ks = 0; ks < 4; ks++) {
            ldmat4(ah[ks], ahi_base + (u32)ks*32);
            ldmat4(al[ks], alo_base + (u32)ks*32);
        }
        __syncwarp();

        float* obase = out + row*RX*DD;
        #pragma unroll
        for (int nt = 0; nt < 8; nt++) {
            float c0 = 0.f, c1 = 0.f, c2 = 0.f, c3 = 0.f;
            #pragma unroll
            for (int ks = 0; ks < 4; ks++) {
                const int idx = (ks*8 + nt)*32 + lane;
                uint2 bh = Bhi[idx];
                uint2 bl = Blo[idx];
                mma_bf16(c0,c1,c2,c3, ah[ks][0],ah[ks][1],ah[ks][2],ah[ks][3], bh.x, bh.y);
                mma_bf16(c0,c1,c2,c3, ah[ks][0],ah[ks][1],ah[ks][2],ah[ks][3], bl.x, bl.y);
                mma_bf16(c0,c1,c2,c3, al[ks][0],al[ks][1],al[ks][2],al[ks][3], bh.x, bh.y);
            }
            const int o0 = nt*8 + t4*2;
            const float2 bb = *(const float2*)(b2s + o0);
            float2 v0; v0.x = c0 + bb.x; v0.y = c1 + bb.y;
            float2 v1; v1.x = c2 + bb.x; v1.y = c3 + bb.y;
            *(float2*)(obase + (size_t)(wid*16 + g)*DD + o0)     = v0;
            *(float2*)(obase + (size_t)(wid*16 + g + 8)*DD + o0) = v1;
        }
    }
}

// -------------------------------------------------------------------------
// Inputs (metadata order): x, W1, b1, ln_g, ln_b, bias, W2, b2
// -------------------------------------------------------------------------
extern "C" void kernel_launch(void* const* d_in, const int* in_sizes, int n_in,
                              void* d_out, int out_size)
{
    const float* x    = (const float*)d_in[0];
    const float* W1   = (const float*)d_in[1];
    const float* b1   = (const float*)d_in[2];
    const float* ln_g = (const float*)d_in[3];
    const float* ln_b = (const float*)d_in[4];
    const float* bias = (const float*)d_in[5];
    const float* W2   = (const float*)d_in[6];
    const float* b2   = (const float*)d_in[7];
    float* out = (float*)d_out;
    (void)in_sizes; (void)n_in; (void)out_size;

    cudaFuncSetAttribute(prep_kernel, cudaFuncAttributeMaxDynamicSharedMemorySize, PREP_SMEM_BYTES);
    cudaFuncSetAttribute(main_mma, cudaFuncAttributeMaxDynamicSharedMemorySize, SM_TOTAL);

    mean_kernel<<<NBU, 256>>>(x, W1, b1);
    prep_kernel<<<dim3(NBU, 8), 512, PREP_SMEM_BYTES>>>(x, W1);
    spb_kernel<<<dim3(NBU, 4), 256>>>();
    main_mma<<<MAIN_GRID, 256, SM_TOTAL>>>(ln_g, ln_b, bias, W2, b2, out);
}